// round 9
// baseline (speedup 1.0000x reference)
#include <cuda_runtime.h>
#include <cuda_fp16.h>
#include <cstdint>

// ---------------------------------------------------------------------------
// MultiAxisAttention (Swin window attention) — fp16 HMMA GEMMs, m16n8k16,
// fp32 accumulate. R9: ldmatrix.x4 fragments, conflict-free cp.async fills,
// 128x256 CTA tile. Attention = R8-proven tf32 HMMA with half I/O.
// ---------------------------------------------------------------------------

#define M_REAL 153664            // 16*196*49
#define M_PAD  153728            // 1201*128
#define NWIN   3136
#define HEADS  16
#define WIN    49
#define KDIM   512

__device__ __half g_qkvh[236027904];   // M_REAL*1536
__device__ __half g_atth[78708736];    // M_PAD*512 (pad rows zeroed)
__device__ __half g_xh  [78708736];    // M_PAD*512 (pad rows zeroed)
__device__ __half g_wqkvT[786432];     // [1536][512]
__device__ __half g_woutT[262144];     // [512][512]

// ------------------------------ helpers -----------------------------------
__device__ __forceinline__ float tf32r(float f) {
    unsigned u;
    asm("cvt.rna.tf32.f32 %0, %1;" : "=r"(u) : "f"(f));
    return __uint_as_float(u);
}
__device__ __forceinline__ uint32_t smem_u32(const void* p) {
    uint32_t a;
    asm("{ .reg .u64 t; cvta.to.shared.u64 t, %1; cvt.u32.u64 %0, t; }"
        : "=r"(a) : "l"(p));
    return a;
}
__device__ __forceinline__ void cp16(uint32_t dst, const void* src) {
    asm volatile("cp.async.cg.shared.global [%0], [%1], 16;\n"
                 :: "r"(dst), "l"(src));
}
#define CP_COMMIT() asm volatile("cp.async.commit_group;\n" ::: "memory")
#define CP_WAIT(n)  asm volatile("cp.async.wait_group %0;\n" :: "n"(n) : "memory")

__device__ __forceinline__ void ldsm4(unsigned* r, uint32_t a) {
    asm volatile("ldmatrix.sync.aligned.m8n8.x4.shared.b16 {%0,%1,%2,%3}, [%4];"
                 : "=r"(r[0]), "=r"(r[1]), "=r"(r[2]), "=r"(r[3]) : "r"(a));
}
__device__ __forceinline__ void mma_f16(float* d, const unsigned* a, const unsigned* b) {
    asm volatile(
        "mma.sync.aligned.m16n8k16.row.col.f32.f16.f16.f32 "
        "{%0,%1,%2,%3}, {%4,%5,%6,%7}, {%8,%9}, {%0,%1,%2,%3};\n"
        : "+f"(d[0]), "+f"(d[1]), "+f"(d[2]), "+f"(d[3])
        : "r"(a[0]), "r"(a[1]), "r"(a[2]), "r"(a[3]),
          "r"(b[0]), "r"(b[1]));
}
__device__ __forceinline__ void mma_tf32(float* d, const unsigned* a, const unsigned* b) {
    asm volatile(
        "mma.sync.aligned.m16n8k8.row.col.f32.tf32.tf32.f32 "
        "{%0,%1,%2,%3}, {%4,%5,%6,%7}, {%8,%9}, {%0,%1,%2,%3};\n"
        : "+f"(d[0]), "+f"(d[1]), "+f"(d[2]), "+f"(d[3])
        : "r"(a[0]), "r"(a[1]), "r"(a[2]), "r"(a[3]),
          "r"(b[0]), "r"(b[1]));
}

__device__ __forceinline__ void storeC(float* C, size_t idx, float a, float b) {
    *(float2*)(C + idx) = make_float2(a, b);
}
__device__ __forceinline__ void storeC(__half* C, size_t idx, float a, float b) {
    *(__half2*)(C + idx) = __floats2half2_rn(a, b);
}

// ----------------------------- GEMM (fp16) ---------------------------------
// CTA tile 128x256, BK=32, 256 threads = 8 warps (2x4), warp tile 64x64.
// A [M][512] half row-major; B = WT [N][512] half row-major.
// smem rows RSH=40 halves: LDSM rows tile all 32 banks; fills conflict-free.
#define BM 128
#define BN 256
#define BK 32
#define RSH 40
#define A_HALVES (BM * RSH)            // 5120
#define B_HALVES (BN * RSH)            // 10240
#define STG_HALVES (A_HALVES + B_HALVES)
#define STG_BYTES (STG_HALVES * 2)     // 30720
#define GSMEM_BYTES (2 * STG_BYTES)    // 61440

template <typename OutT>
__global__ void __launch_bounds__(256)
gemm_f16(const __half* __restrict__ A, const __half* __restrict__ B,
         OutT* __restrict__ C, int Mreal, int N)
{
    extern __shared__ __half sm[];

    const int tid  = threadIdx.x;
    const int lane = tid & 31;
    const int warp = tid >> 5;          // 0..7
    const int wm   = warp >> 2;         // 0..1
    const int wn   = warp & 3;          // 0..3
    const int grp  = lane >> 2;
    const int tg   = lane & 3;

    const int m0 = blockIdx.y * BM;
    const int n0 = blockIdx.x * BN;
    const uint32_t smb = smem_u32(sm);

    // fill geometry: per rep a warp covers 8 full rows (64B each);
    // lane -> row = lane&7, 16B chunk = lane>>3  (slots (5r+c)%8 all distinct)
    const int fr = lane & 7;
    const int fc = (lane >> 3) << 3;    // halves: 0,8,16,24
    const int frow = warp * 8 + fr;     // 0..63 base
    const __half*  ag0 = A + (size_t)(m0 + frow) * KDIM + fc;
    const __half*  bg0 = B + (size_t)(n0 + frow) * KDIM + fc;
    const uint32_t ad0 = smb + (uint32_t)((frow * RSH + fc) * 2);
    const uint32_t bd0 = smb + (uint32_t)(A_HALVES * 2) + (uint32_t)((frow * RSH + fc) * 2);

    // ldmatrix lane->address components
    const int l7 = lane & 7;
    const int lb = (lane >> 3) & 1;
    const int lt = lane >> 4;
    // A x4: m0..7/m8..15 x k0..7/k8..15  -> {a0,a1,a2,a3}
    const uint32_t aL = smb +
        (uint32_t)(((wm * 64 + l7 + lb * 8) * RSH + lt * 8) * 2);
    // B x4 on WT rows: (nt rows / nt+1 rows) x (k0-7 / k8-15) -> {b0,b1,b0',b1'}
    const uint32_t bL = smb + (uint32_t)(A_HALVES * 2) +
        (uint32_t)(((wn * 64 + l7 + lt * 8) * RSH + lb * 8) * 2);

    float acc[4][8][4];
    #pragma unroll
    for (int i = 0; i < 4; i++)
        #pragma unroll
        for (int j = 0; j < 8; j++)
            #pragma unroll
            for (int l = 0; l < 4; l++) acc[i][j][l] = 0.f;

    const int T = KDIM / BK;   // 16

    // prologue: stage 0 -> buffer 0
    #pragma unroll
    for (int p = 0; p < 2; p++)
        cp16(ad0 + (uint32_t)(p * 64 * RSH) * 2, ag0 + (size_t)p * 64 * KDIM);
    #pragma unroll
    for (int p = 0; p < 4; p++)
        cp16(bd0 + (uint32_t)(p * 64 * RSH) * 2, bg0 + (size_t)p * 64 * KDIM);
    CP_COMMIT();

    for (int t = 0; t < T; ++t) {
        const int buf = t & 1;

        if (t + 1 < T) {
            const int nb = (t + 1) & 1;
            const int kb = (t + 1) * BK;
            const uint32_t ad = ad0 + (uint32_t)nb * STG_BYTES;
            const uint32_t bd = bd0 + (uint32_t)nb * STG_BYTES;
            const __half* ag = ag0 + kb;
            const __half* bg = bg0 + kb;
            #pragma unroll
            for (int p = 0; p < 2; p++)
                cp16(ad + (uint32_t)(p * 64 * RSH) * 2, ag + (size_t)p * 64 * KDIM);
            #pragma unroll
            for (int p = 0; p < 4; p++)
                cp16(bd + (uint32_t)(p * 64 * RSH) * 2, bg + (size_t)p * 64 * KDIM);
            CP_COMMIT();
            CP_WAIT(1);
        } else {
            CP_WAIT(0);
        }
        __syncthreads();

        const uint32_t aB = aL + (uint32_t)buf * STG_BYTES;
        const uint32_t bB = bL + (uint32_t)buf * STG_BYTES;
        #pragma unroll
        for (int ks = 0; ks < 2; ks++) {
            const uint32_t kkb = (uint32_t)(ks * 32);     // 16 halves
            unsigned af[4][4], bf[8][2];
            #pragma unroll
            for (int mt = 0; mt < 4; mt++)
                ldsm4(af[mt], aB + (uint32_t)(mt * 16 * RSH * 2) + kkb);
            #pragma unroll
            for (int np = 0; np < 4; np++) {
                unsigned r[4];
                ldsm4(r, bB + (uint32_t)(np * 16 * RSH * 2) + kkb);
                bf[2 * np][0] = r[0]; bf[2 * np][1] = r[1];
                bf[2 * np + 1][0] = r[2]; bf[2 * np + 1][1] = r[3];
            }
            #pragma unroll
            for (int mt = 0; mt < 4; mt++)
                #pragma unroll
                for (int nt = 0; nt < 8; nt++)
                    mma_f16(acc[mt][nt], af[mt], bf[nt]);
        }
        __syncthreads();
    }

    #pragma unroll
    for (int mt = 0; mt < 4; mt++) {
        #pragma unroll
        for (int nt = 0; nt < 8; nt++) {
            int r0 = m0 + wm * 64 + mt * 16 + grp;
            int c  = n0 + wn * 64 + nt * 8 + tg * 2;
            if (r0 < Mreal)
                storeC(C, (size_t)r0 * N + c, acc[mt][nt][0], acc[mt][nt][1]);
            if (r0 + 8 < Mreal)
                storeC(C, (size_t)(r0 + 8) * N + c, acc[mt][nt][2], acc[mt][nt][3]);
        }
    }
}

// ------------------------------ prep kernels -------------------------------
__global__ void half_pad(const float* __restrict__ x, __half* __restrict__ xh,
                         long nreal, long ntot)
{
    long i = (long)blockIdx.x * blockDim.x + threadIdx.x;
    if (i < ntot) xh[i] = __float2half((i < nreal) ? x[i] : 0.f);
}

__global__ void transpose_half(const float* __restrict__ W, __half* __restrict__ WT,
                               int R, int Ccols)
{
    __shared__ float t[32][33];
    const int tx = threadIdx.x, ty = threadIdx.y;
    const int x = blockIdx.x * 32 + tx;
    #pragma unroll
    for (int j = 0; j < 4; j++) {
        int y = blockIdx.y * 32 + ty + j * 8;
        t[ty + j * 8][tx] = W[(size_t)y * Ccols + x];
    }
    __syncthreads();
    const int ox = blockIdx.y * 32 + tx;
    #pragma unroll
    for (int j = 0; j < 4; j++) {
        int oy = blockIdx.x * 32 + ty + j * 8;
        WT[(size_t)oy * R + ox] = __float2half(t[tx][ty + j * 8]);
    }
}

__global__ void zero_fill_h(__half* __restrict__ p, int n)
{
    int i = blockIdx.x * blockDim.x + threadIdx.x;
    if (i < n / 2) ((uint32_t*)p)[i] = 0u;
}

// ----------------------------- attention (tf32 HMMA, half I/O) -------------
#define QST 36
#define KST 36
#define VST 40
#define PST 60

__device__ __forceinline__ int div7(int v) { return (v * 37) >> 8; }  // exact 0..55

__global__ void __launch_bounds__(128)
attn_mma(const __half* __restrict__ qkv,
         const float* __restrict__ bias_table,
         __half* __restrict__ att)
{
    __shared__ float Qs[64 * QST];
    __shared__ float Ks[56 * KST];
    __shared__ float Vs[56 * VST];
    __shared__ float Ps[64 * PST];
    __shared__ float bs[176];
    __shared__ float inv[64];

    const int h  = blockIdx.x & 15;
    const int bw = blockIdx.x >> 4;
    const int tid  = threadIdx.x;
    const int lane = tid & 31;
    const int wm   = tid >> 5;
    const int grp  = lane >> 2;
    const int tg   = lane & 3;

    const __half* base = qkv + (size_t)bw * WIN * 1536 + h * 32;
    const float SCALE = 0.17677669529663687f;

    for (int l = tid; l < WIN * 4; l += 128) {
        int i = l >> 2, c = l & 3;
        const __half2* qrow = (const __half2*)(base + (size_t)i * 1536) + c * 4;
        const __half2* krow = (const __half2*)(base + (size_t)i * 1536 + 512) + c * 4;
        const __half2* vrow = (const __half2*)(base + (size_t)i * 1536 + 1024) + c * 4;
        #pragma unroll
        for (int q = 0; q < 4; q++) {
            float2 qf = __half22float2(qrow[q]);
            Qs[i * QST + c * 8 + 2 * q]     = tf32r(qf.x * SCALE);
            Qs[i * QST + c * 8 + 2 * q + 1] = tf32r(qf.y * SCALE);
            float2 kf = __half22float2(krow[q]);
            Ks[i * KST + c * 8 + 2 * q]     = kf.x;
            Ks[i * KST + c * 8 + 2 * q + 1] = kf.y;
            float2 vf = __half22float2(vrow[q]);
            Vs[i * VST + c * 8 + 2 * q]     = vf.x;
            Vs[i * VST + c * 8 + 2 * q + 1] = vf.y;
        }
    }
    const float4 z4 = make_float4(0.f, 0.f, 0.f, 0.f);
    for (int l = tid; l < 15 * 8; l += 128) {
        int i = WIN + (l >> 3), c = l & 7;
        *(float4*)(Qs + i * QST + c * 4) = z4;
        if (i < 56) {
            *(float4*)(Ks + i * KST + c * 4) = z4;
            *(float4*)(Vs + i * VST + c * 4) = z4;
        }
    }
    for (int l = tid; l < 169; l += 128) bs[l] = bias_table[l * HEADS + h];
    __syncthreads();

    const int i0 = wm * 16 + grp;
    const int i1 = i0 + 8;
    const int ri0 = div7(i0), ci0 = i0 - ri0 * 7;
    const int ri1 = div7(i1), ci1 = i1 - ri1 * 7;

    float c[7][4];
    #pragma unroll
    for (int nt = 0; nt < 7; nt++)
        #pragma unroll
        for (int l = 0; l < 4; l++) c[nt][l] = 0.f;

    #pragma unroll
    for (int ks = 0; ks < 4; ks++) {
        const int kk = ks * 8;
        unsigned a[4];
        a[0] = __float_as_uint(Qs[i0 * QST + kk + tg]);
        a[1] = __float_as_uint(Qs[i1 * QST + kk + tg]);
        a[2] = __float_as_uint(Qs[i0 * QST + kk + tg + 4]);
        a[3] = __float_as_uint(Qs[i1 * QST + kk + tg + 4]);
        #pragma unroll
        for (int nt = 0; nt < 7; nt++) {
            const int j = nt * 8 + grp;
            unsigned b[2];
            b[0] = __float_as_uint(Ks[j * KST + kk + tg]);
            b[1] = __float_as_uint(Ks[j * KST + kk + tg + 4]);
            mma_tf32(c[nt], a, b);
        }
    }

    float s01 = 0.f, s23 = 0.f;
    #pragma unroll
    for (int nt = 0; nt < 7; nt++) {
        const int j0 = nt * 8 + 2 * tg;
        const int j1 = j0 + 1;
        const int rj0 = div7(j0), cj0 = j0 - rj0 * 7;
        const int rj1 = div7(j1), cj1 = j1 - rj1 * 7;
        float e00 = 0.f, e01 = 0.f, e10 = 0.f, e11 = 0.f;
        if (j0 < WIN) {
            e00 = __expf(c[nt][0] + bs[(ri0 - rj0 + 6) * 13 + (ci0 - cj0 + 6)]);
            e10 = __expf(c[nt][2] + bs[(ri1 - rj0 + 6) * 13 + (ci1 - cj0 + 6)]);
        }
        if (j1 < WIN) {
            e01 = __expf(c[nt][1] + bs[(ri0 - rj1 + 6) * 13 + (ci0 - cj1 + 6)]);
            e11 = __expf(c[nt][3] + bs[(ri1 - rj1 + 6) * 13 + (ci1 - cj1 + 6)]);
        }
        s01 += e00 + e01;
        s23 += e10 + e11;
        *(float2*)(Ps + i0 * PST + j0) = make_float2(tf32r(e00), tf32r(e01));
        *(float2*)(Ps + i1 * PST + j0) = make_float2(tf32r(e10), tf32r(e11));
    }
    s01 += __shfl_xor_sync(0xFFFFFFFFu, s01, 1);
    s01 += __shfl_xor_sync(0xFFFFFFFFu, s01, 2);
    s23 += __shfl_xor_sync(0xFFFFFFFFu, s23, 1);
    s23 += __shfl_xor_sync(0xFFFFFFFFu, s23, 2);
    if (tg == 0) {
        inv[i0] = 1.f / s01;
        inv[i1] = 1.f / s23;
    }
    __syncwarp();

    float o[4][4];
    #pragma unroll
    for (int nt = 0; nt < 4; nt++)
        #pragma unroll
        for (int l = 0; l < 4; l++) o[nt][l] = 0.f;

    #pragma unroll
    for (int ks = 0; ks < 7; ks++) {
        const int kk = ks * 8;
        unsigned a[4];
        a[0] = __float_as_uint(Ps[i0 * PST + kk + tg]);
        a[1] = __float_as_uint(Ps[i1 * PST + kk + tg]);
        a[2] = __float_as_uint(Ps[i0 * PST + kk + tg + 4]);
        a[3] = __float_as_uint(Ps[i1 * PST + kk + tg + 4]);
        #pragma unroll
        for (int nt = 0; nt < 4; nt++) {
            unsigned b[2];
            b[0] = __float_as_uint(Vs[(kk + tg)     * VST + nt * 8 + grp]);
            b[1] = __float_as_uint(Vs[(kk + tg + 4) * VST + nt * 8 + grp]);
            mma_tf32(o[nt], a, b);
        }
    }

    const float v0 = inv[i0];
    const float v1 = inv[i1];
    __half* obase = att + (size_t)bw * WIN * 512 + h * 32;
    #pragma unroll
    for (int nt = 0; nt < 4; nt++) {
        const int d0 = nt * 8 + 2 * tg;
        if (i0 < WIN)
            *(__half2*)(obase + (size_t)i0 * 512 + d0) =
                __floats2half2_rn(o[nt][0] * v0, o[nt][1] * v0);
        if (i1 < WIN)
            *(__half2*)(obase + (size_t)i1 * 512 + d0) =
                __floats2half2_rn(o[nt][2] * v1, o[nt][3] * v1);
    }
}

// --------------------------------- launcher --------------------------------
extern "C" void kernel_launch(void* const* d_in, const int* in_sizes, int n_in,
                              void* d_out, int out_size)
{
    const float* x          = (const float*)d_in[0];
    const float* w_qkv      = (const float*)d_in[1];
    const float* bias_table = (const float*)d_in[2];
    const float* w_out      = (const float*)d_in[3];
    float* out = (float*)d_out;

    __half *qkvh, *atth, *xh, *wqkvT, *woutT;
    cudaGetSymbolAddress((void**)&qkvh,  g_qkvh);
    cudaGetSymbolAddress((void**)&atth,  g_atth);
    cudaGetSymbolAddress((void**)&xh,    g_xh);
    cudaGetSymbolAddress((void**)&wqkvT, g_wqkvT);
    cudaGetSymbolAddress((void**)&woutT, g_woutT);

    cudaFuncSetAttribute(gemm_f16<__half>,
                         cudaFuncAttributeMaxDynamicSharedMemorySize, GSMEM_BYTES);
    cudaFuncSetAttribute(gemm_f16<float>,
                         cudaFuncAttributeMaxDynamicSharedMemorySize, GSMEM_BYTES);

    const long nreal = (long)M_REAL * 512;
    const long ntot  = (long)M_PAD  * 512;

    half_pad<<<(int)((ntot + 255) / 256), 256>>>(x, xh, nreal, ntot);
    transpose_half<<<dim3(1536 / 32, 512 / 32), dim3(32, 8)>>>(w_qkv, wqkvT, 512, 1536);
    transpose_half<<<dim3(512 / 32, 512 / 32), dim3(32, 8)>>>(w_out, woutT, 512, 512);
    zero_fill_h<<<(64 * 512 / 2 + 255) / 256, 256>>>(atth + nreal, 64 * 512);

    // K1: qkvh = xh @ wqkvT^T
    gemm_f16<__half><<<dim3(1536 / BN, M_PAD / BM), 256, GSMEM_BYTES>>>(
        xh, wqkvT, qkvh, M_REAL, 1536);

    // K2: attention
    attn_mma<<<NWIN * HEADS, 128>>>(qkvh, bias_table, atth);

    // K3: out = atth @ woutT^T
    gemm_f16<float><<<dim3(512 / BN, M_PAD / BM), 256, GSMEM_BYTES>>>(
        atth, woutT, out, M_REAL, 512);
}

// round 10
// speedup vs baseline: 1.0341x; 1.0341x over previous
#include <cuda_runtime.h>
#include <cuda_fp16.h>
#include <cstdint>

// ---------------------------------------------------------------------------
// MultiAxisAttention (Swin window attention) — fp16 HMMA GEMMs, m16n8k16,
// fp32 accumulate. R10 = R8 occupancy shape (128x128, 128 thr, 40KB smem)
// + R9 micro-opts (ldmatrix.x4 fragments, conflict-free cp.async fills).
// Attention = R8-proven tf32 HMMA with half I/O.
// ---------------------------------------------------------------------------

#define M_REAL 153664            // 16*196*49
#define M_PAD  153728            // 1201*128
#define NWIN   3136
#define HEADS  16
#define WIN    49
#define KDIM   512

__device__ __half g_qkvh[236027904];   // M_REAL*1536
__device__ __half g_atth[78708736];    // M_PAD*512 (pad rows zeroed)
__device__ __half g_xh  [78708736];    // M_PAD*512 (pad rows zeroed)
__device__ __half g_wqkvT[786432];     // [1536][512]
__device__ __half g_woutT[262144];     // [512][512]

// ------------------------------ helpers -----------------------------------
__device__ __forceinline__ float tf32r(float f) {
    unsigned u;
    asm("cvt.rna.tf32.f32 %0, %1;" : "=r"(u) : "f"(f));
    return __uint_as_float(u);
}
__device__ __forceinline__ uint32_t smem_u32(const void* p) {
    uint32_t a;
    asm("{ .reg .u64 t; cvta.to.shared.u64 t, %1; cvt.u32.u64 %0, t; }"
        : "=r"(a) : "l"(p));
    return a;
}
__device__ __forceinline__ void cp16(uint32_t dst, const void* src) {
    asm volatile("cp.async.cg.shared.global [%0], [%1], 16;\n"
                 :: "r"(dst), "l"(src));
}
#define CP_COMMIT() asm volatile("cp.async.commit_group;\n" ::: "memory")
#define CP_WAIT(n)  asm volatile("cp.async.wait_group %0;\n" :: "n"(n) : "memory")

__device__ __forceinline__ void ldsm4(unsigned* r, uint32_t a) {
    asm volatile("ldmatrix.sync.aligned.m8n8.x4.shared.b16 {%0,%1,%2,%3}, [%4];"
                 : "=r"(r[0]), "=r"(r[1]), "=r"(r[2]), "=r"(r[3]) : "r"(a));
}
__device__ __forceinline__ void mma_f16(float* d, const unsigned* a, const unsigned* b) {
    asm volatile(
        "mma.sync.aligned.m16n8k16.row.col.f32.f16.f16.f32 "
        "{%0,%1,%2,%3}, {%4,%5,%6,%7}, {%8,%9}, {%0,%1,%2,%3};\n"
        : "+f"(d[0]), "+f"(d[1]), "+f"(d[2]), "+f"(d[3])
        : "r"(a[0]), "r"(a[1]), "r"(a[2]), "r"(a[3]),
          "r"(b[0]), "r"(b[1]));
}
__device__ __forceinline__ void mma_tf32(float* d, const unsigned* a, const unsigned* b) {
    asm volatile(
        "mma.sync.aligned.m16n8k8.row.col.f32.tf32.tf32.f32 "
        "{%0,%1,%2,%3}, {%4,%5,%6,%7}, {%8,%9}, {%0,%1,%2,%3};\n"
        : "+f"(d[0]), "+f"(d[1]), "+f"(d[2]), "+f"(d[3])
        : "r"(a[0]), "r"(a[1]), "r"(a[2]), "r"(a[3]),
          "r"(b[0]), "r"(b[1]));
}

__device__ __forceinline__ void storeC(float* C, size_t idx, float a, float b) {
    *(float2*)(C + idx) = make_float2(a, b);
}
__device__ __forceinline__ void storeC(__half* C, size_t idx, float a, float b) {
    *(__half2*)(C + idx) = __floats2half2_rn(a, b);
}

// ----------------------------- GEMM (fp16) ---------------------------------
// CTA 128x128, BK=32, 128 threads = 4 warps (2x2), warp tile 64x64.
// A [M][512] half row-major; B = WT [N][512] half row-major.
// RSH=40: LDSM rows tile 32 banks; fill slots (5r+c)%8 distinct per warp.
#define BM 128
#define BN 128
#define BK 32
#define RSH 40
#define OP_HALVES (128 * RSH)          // 5120 per operand per stage
#define STG_HALVES (2 * OP_HALVES)     // A|B per stage
#define STG_BYTES (STG_HALVES * 2)     // 20480

template <typename OutT>
__global__ void __launch_bounds__(128)
gemm_f16(const __half* __restrict__ A, const __half* __restrict__ B,
         OutT* __restrict__ C, int Mreal, int N)
{
    __shared__ __half sm[2 * STG_HALVES];   // 40 KB

    const int tid  = threadIdx.x;
    const int lane = tid & 31;
    const int warp = tid >> 5;          // 0..3
    const int wm   = warp >> 1;
    const int wn   = warp & 1;
    const int grp  = lane >> 2;
    const int tg   = lane & 3;

    const int m0 = blockIdx.y * BM;
    const int n0 = blockIdx.x * BN;
    const uint32_t smb = smem_u32(sm);

    // conflict-free fill: warp covers 8 rows x 64B; lane -> row=lane&7, chunk=lane>>3
    const int frow = warp * 8 + (lane & 7);     // base row, reps +32p (p<4)
    const int fc   = (lane >> 3) << 3;          // halves: 0,8,16,24
    const __half*  ag0 = A + (size_t)(m0 + frow) * KDIM + fc;
    const __half*  bg0 = B + (size_t)(n0 + frow) * KDIM + fc;
    const uint32_t ad0 = smb + (uint32_t)((frow * RSH + fc) * 2);
    const uint32_t bd0 = ad0 + OP_HALVES * 2;

    // ldmatrix lane->address components
    const int l7 = lane & 7;
    const int lb = (lane >> 3) & 1;
    const int lt = lane >> 4;
    // A x4: (m0..7 / m8..15) x (k0..7 / k8..15) -> {a0,a1,a2,a3}
    const uint32_t aL = smb +
        (uint32_t)(((wm * 64 + l7 + lb * 8) * RSH + lt * 8) * 2);
    // B x4 on WT rows: (nt / nt+1 row-groups) x (k0-7 / k8-15) -> {b0,b1,b0',b1'}
    const uint32_t bL = smb + (uint32_t)(OP_HALVES * 2) +
        (uint32_t)(((wn * 64 + l7 + lt * 8) * RSH + lb * 8) * 2);

    float acc[4][8][4];
    #pragma unroll
    for (int i = 0; i < 4; i++)
        #pragma unroll
        for (int j = 0; j < 8; j++)
            #pragma unroll
            for (int l = 0; l < 4; l++) acc[i][j][l] = 0.f;

    const int T = KDIM / BK;   // 16

    #pragma unroll
    for (int p = 0; p < 4; p++) {
        cp16(ad0 + (uint32_t)(p * 32 * RSH) * 2, ag0 + (size_t)p * 32 * KDIM);
        cp16(bd0 + (uint32_t)(p * 32 * RSH) * 2, bg0 + (size_t)p * 32 * KDIM);
    }
    CP_COMMIT();

    for (int t = 0; t < T; ++t) {
        const int buf = t & 1;

        if (t + 1 < T) {
            const int nb = (t + 1) & 1;
            const int kb = (t + 1) * BK;
            const uint32_t ad = ad0 + (uint32_t)nb * STG_BYTES;
            const uint32_t bd = bd0 + (uint32_t)nb * STG_BYTES;
            const __half* ag = ag0 + kb;
            const __half* bg = bg0 + kb;
            #pragma unroll
            for (int p = 0; p < 4; p++) {
                cp16(ad + (uint32_t)(p * 32 * RSH) * 2, ag + (size_t)p * 32 * KDIM);
                cp16(bd + (uint32_t)(p * 32 * RSH) * 2, bg + (size_t)p * 32 * KDIM);
            }
            CP_COMMIT();
            CP_WAIT(1);
        } else {
            CP_WAIT(0);
        }
        __syncthreads();

        const uint32_t aB = aL + (uint32_t)buf * STG_BYTES;
        const uint32_t bB = bL + (uint32_t)buf * STG_BYTES;
        #pragma unroll
        for (int ks = 0; ks < 2; ks++) {
            const uint32_t kkb = (uint32_t)(ks * 32);     // 16 halves
            unsigned af[4][4], bf[8][2];
            #pragma unroll
            for (int mt = 0; mt < 4; mt++)
                ldsm4(af[mt], aB + (uint32_t)(mt * 16 * RSH * 2) + kkb);
            #pragma unroll
            for (int np = 0; np < 4; np++) {
                unsigned r[4];
                ldsm4(r, bB + (uint32_t)(np * 16 * RSH * 2) + kkb);
                bf[2 * np][0] = r[0]; bf[2 * np][1] = r[1];
                bf[2 * np + 1][0] = r[2]; bf[2 * np + 1][1] = r[3];
            }
            #pragma unroll
            for (int mt = 0; mt < 4; mt++)
                #pragma unroll
                for (int nt = 0; nt < 8; nt++)
                    mma_f16(acc[mt][nt], af[mt], bf[nt]);
        }
        __syncthreads();
    }

    #pragma unroll
    for (int mt = 0; mt < 4; mt++) {
        #pragma unroll
        for (int nt = 0; nt < 8; nt++) {
            int r0 = m0 + wm * 64 + mt * 16 + grp;
            int c  = n0 + wn * 64 + nt * 8 + tg * 2;
            if (r0 < Mreal)
                storeC(C, (size_t)r0 * N + c, acc[mt][nt][0], acc[mt][nt][1]);
            if (r0 + 8 < Mreal)
                storeC(C, (size_t)(r0 + 8) * N + c, acc[mt][nt][2], acc[mt][nt][3]);
        }
    }
}

// ------------------------------ prep kernels -------------------------------
__global__ void half_pad(const float* __restrict__ x, __half* __restrict__ xh,
                         long nreal, long ntot)
{
    long i = (long)blockIdx.x * blockDim.x + threadIdx.x;
    if (i < ntot) xh[i] = __float2half((i < nreal) ? x[i] : 0.f);
}

__global__ void transpose_half(const float* __restrict__ W, __half* __restrict__ WT,
                               int R, int Ccols)
{
    __shared__ float t[32][33];
    const int tx = threadIdx.x, ty = threadIdx.y;
    const int x = blockIdx.x * 32 + tx;
    #pragma unroll
    for (int j = 0; j < 4; j++) {
        int y = blockIdx.y * 32 + ty + j * 8;
        t[ty + j * 8][tx] = W[(size_t)y * Ccols + x];
    }
    __syncthreads();
    const int ox = blockIdx.y * 32 + tx;
    #pragma unroll
    for (int j = 0; j < 4; j++) {
        int oy = blockIdx.x * 32 + ty + j * 8;
        WT[(size_t)oy * R + ox] = __float2half(t[tx][ty + j * 8]);
    }
}

__global__ void zero_fill_h(__half* __restrict__ p, int n)
{
    int i = blockIdx.x * blockDim.x + threadIdx.x;
    if (i < n / 2) ((uint32_t*)p)[i] = 0u;
}

// ----------------------------- attention (tf32 HMMA, half I/O) -------------
#define QST 36
#define KST 36
#define VST 40
#define PST 60

__device__ __forceinline__ int div7(int v) { return (v * 37) >> 8; }  // exact 0..55

__global__ void __launch_bounds__(128)
attn_mma(const __half* __restrict__ qkv,
         const float* __restrict__ bias_table,
         __half* __restrict__ att)
{
    __shared__ float Qs[64 * QST];
    __shared__ float Ks[56 * KST];
    __shared__ float Vs[56 * VST];
    __shared__ float Ps[64 * PST];
    __shared__ float bs[176];
    __shared__ float inv[64];

    const int h  = blockIdx.x & 15;
    const int bw = blockIdx.x >> 4;
    const int tid  = threadIdx.x;
    const int lane = tid & 31;
    const int wm   = tid >> 5;
    const int grp  = lane >> 2;
    const int tg   = lane & 3;

    const __half* base = qkv + (size_t)bw * WIN * 1536 + h * 32;
    const float SCALE = 0.17677669529663687f;

    for (int l = tid; l < WIN * 4; l += 128) {
        int i = l >> 2, c = l & 3;
        const __half2* qrow = (const __half2*)(base + (size_t)i * 1536) + c * 4;
        const __half2* krow = (const __half2*)(base + (size_t)i * 1536 + 512) + c * 4;
        const __half2* vrow = (const __half2*)(base + (size_t)i * 1536 + 1024) + c * 4;
        #pragma unroll
        for (int q = 0; q < 4; q++) {
            float2 qf = __half22float2(qrow[q]);
            Qs[i * QST + c * 8 + 2 * q]     = tf32r(qf.x * SCALE);
            Qs[i * QST + c * 8 + 2 * q + 1] = tf32r(qf.y * SCALE);
            float2 kf = __half22float2(krow[q]);
            Ks[i * KST + c * 8 + 2 * q]     = kf.x;
            Ks[i * KST + c * 8 + 2 * q + 1] = kf.y;
            float2 vf = __half22float2(vrow[q]);
            Vs[i * VST + c * 8 + 2 * q]     = vf.x;
            Vs[i * VST + c * 8 + 2 * q + 1] = vf.y;
        }
    }
    const float4 z4 = make_float4(0.f, 0.f, 0.f, 0.f);
    for (int l = tid; l < 15 * 8; l += 128) {
        int i = WIN + (l >> 3), c = l & 7;
        *(float4*)(Qs + i * QST + c * 4) = z4;
        if (i < 56) {
            *(float4*)(Ks + i * KST + c * 4) = z4;
            *(float4*)(Vs + i * VST + c * 4) = z4;
        }
    }
    for (int l = tid; l < 169; l += 128) bs[l] = bias_table[l * HEADS + h];
    __syncthreads();

    const int i0 = wm * 16 + grp;
    const int i1 = i0 + 8;
    const int ri0 = div7(i0), ci0 = i0 - ri0 * 7;
    const int ri1 = div7(i1), ci1 = i1 - ri1 * 7;

    float c[7][4];
    #pragma unroll
    for (int nt = 0; nt < 7; nt++)
        #pragma unroll
        for (int l = 0; l < 4; l++) c[nt][l] = 0.f;

    #pragma unroll
    for (int ks = 0; ks < 4; ks++) {
        const int kk = ks * 8;
        unsigned a[4];
        a[0] = __float_as_uint(Qs[i0 * QST + kk + tg]);
        a[1] = __float_as_uint(Qs[i1 * QST + kk + tg]);
        a[2] = __float_as_uint(Qs[i0 * QST + kk + tg + 4]);
        a[3] = __float_as_uint(Qs[i1 * QST + kk + tg + 4]);
        #pragma unroll
        for (int nt = 0; nt < 7; nt++) {
            const int j = nt * 8 + grp;
            unsigned b[2];
            b[0] = __float_as_uint(Ks[j * KST + kk + tg]);
            b[1] = __float_as_uint(Ks[j * KST + kk + tg + 4]);
            mma_tf32(c[nt], a, b);
        }
    }

    float s01 = 0.f, s23 = 0.f;
    #pragma unroll
    for (int nt = 0; nt < 7; nt++) {
        const int j0 = nt * 8 + 2 * tg;
        const int j1 = j0 + 1;
        const int rj0 = div7(j0), cj0 = j0 - rj0 * 7;
        const int rj1 = div7(j1), cj1 = j1 - rj1 * 7;
        float e00 = 0.f, e01 = 0.f, e10 = 0.f, e11 = 0.f;
        if (j0 < WIN) {
            e00 = __expf(c[nt][0] + bs[(ri0 - rj0 + 6) * 13 + (ci0 - cj0 + 6)]);
            e10 = __expf(c[nt][2] + bs[(ri1 - rj0 + 6) * 13 + (ci1 - cj0 + 6)]);
        }
        if (j1 < WIN) {
            e01 = __expf(c[nt][1] + bs[(ri0 - rj1 + 6) * 13 + (ci0 - cj1 + 6)]);
            e11 = __expf(c[nt][3] + bs[(ri1 - rj1 + 6) * 13 + (ci1 - cj1 + 6)]);
        }
        s01 += e00 + e01;
        s23 += e10 + e11;
        *(float2*)(Ps + i0 * PST + j0) = make_float2(tf32r(e00), tf32r(e01));
        *(float2*)(Ps + i1 * PST + j0) = make_float2(tf32r(e10), tf32r(e11));
    }
    s01 += __shfl_xor_sync(0xFFFFFFFFu, s01, 1);
    s01 += __shfl_xor_sync(0xFFFFFFFFu, s01, 2);
    s23 += __shfl_xor_sync(0xFFFFFFFFu, s23, 1);
    s23 += __shfl_xor_sync(0xFFFFFFFFu, s23, 2);
    if (tg == 0) {
        inv[i0] = 1.f / s01;
        inv[i1] = 1.f / s23;
    }
    __syncwarp();

    float o[4][4];
    #pragma unroll
    for (int nt = 0; nt < 4; nt++)
        #pragma unroll
        for (int l = 0; l < 4; l++) o[nt][l] = 0.f;

    #pragma unroll
    for (int ks = 0; ks < 7; ks++) {
        const int kk = ks * 8;
        unsigned a[4];
        a[0] = __float_as_uint(Ps[i0 * PST + kk + tg]);
        a[1] = __float_as_uint(Ps[i1 * PST + kk + tg]);
        a[2] = __float_as_uint(Ps[i0 * PST + kk + tg + 4]);
        a[3] = __float_as_uint(Ps[i1 * PST + kk + tg + 4]);
        #pragma unroll
        for (int nt = 0; nt < 4; nt++) {
            unsigned b[2];
            b[0] = __float_as_uint(Vs[(kk + tg)     * VST + nt * 8 + grp]);
            b[1] = __float_as_uint(Vs[(kk + tg + 4) * VST + nt * 8 + grp]);
            mma_tf32(o[nt], a, b);
        }
    }

    const float v0 = inv[i0];
    const float v1 = inv[i1];
    __half* obase = att + (size_t)bw * WIN * 512 + h * 32;
    #pragma unroll
    for (int nt = 0; nt < 4; nt++) {
        const int d0 = nt * 8 + 2 * tg;
        if (i0 < WIN)
            *(__half2*)(obase + (size_t)i0 * 512 + d0) =
                __floats2half2_rn(o[nt][0] * v0, o[nt][1] * v0);
        if (i1 < WIN)
            *(__half2*)(obase + (size_t)i1 * 512 + d0) =
                __floats2half2_rn(o[nt][2] * v1, o[nt][3] * v1);
    }
}

// --------------------------------- launcher --------------------------------
extern "C" void kernel_launch(void* const* d_in, const int* in_sizes, int n_in,
                              void* d_out, int out_size)
{
    const float* x          = (const float*)d_in[0];
    const float* w_qkv      = (const float*)d_in[1];
    const float* bias_table = (const float*)d_in[2];
    const float* w_out      = (const float*)d_in[3];
    float* out = (float*)d_out;

    __half *qkvh, *atth, *xh, *wqkvT, *woutT;
    cudaGetSymbolAddress((void**)&qkvh,  g_qkvh);
    cudaGetSymbolAddress((void**)&atth,  g_atth);
    cudaGetSymbolAddress((void**)&xh,    g_xh);
    cudaGetSymbolAddress((void**)&wqkvT, g_wqkvT);
    cudaGetSymbolAddress((void**)&woutT, g_woutT);

    const long nreal = (long)M_REAL * 512;
    const long ntot  = (long)M_PAD  * 512;

    half_pad<<<(int)((ntot + 255) / 256), 256>>>(x, xh, nreal, ntot);
    transpose_half<<<dim3(1536 / 32, 512 / 32), dim3(32, 8)>>>(w_qkv, wqkvT, 512, 1536);
    transpose_half<<<dim3(512 / 32, 512 / 32), dim3(32, 8)>>>(w_out, woutT, 512, 512);
    zero_fill_h<<<(64 * 512 / 2 + 255) / 256, 256>>>(atth + nreal, 64 * 512);

    // K1: qkvh = xh @ wqkvT^T
    gemm_f16<__half><<<dim3(1536 / BN, M_PAD / BM), 128>>>(
        xh, wqkvT, qkvh, M_REAL, 1536);

    // K2: attention
    attn_mma<<<NWIN * HEADS, 128>>>(qkvh, bias_table, atth);

    // K3: out = atth @ woutT^T
    gemm_f16<float><<<dim3(512 / BN, M_PAD / BM), 128>>>(
        atth, woutT, out, M_REAL, 512);
}

// round 11
// speedup vs baseline: 1.0390x; 1.0048x over previous
#include <cuda_runtime.h>
#include <cuda_fp16.h>
#include <cstdint>

// ---------------------------------------------------------------------------
// MultiAxisAttention (Swin window attention) — fp16 HMMA GEMMs, m16n8k16,
// fp32 accumulate. R11 = R10 + 4-stage cp.async ring (single sync/stage).
// Attention = R8-proven tf32 HMMA with half I/O.
// Launch order tuned so the ncu capture slot lands on gemm K1.
// ---------------------------------------------------------------------------

#define M_REAL 153664            // 16*196*49
#define M_PAD  153728            // 1201*128
#define NWIN   3136
#define HEADS  16
#define WIN    49
#define KDIM   512

__device__ __half g_qkvh[236027904];   // M_REAL*1536
__device__ __half g_atth[78708736];    // M_PAD*512 (pad rows zeroed)
__device__ __half g_xh  [78708736];    // M_PAD*512 (pad rows zeroed)
__device__ __half g_wqkvT[786432];     // [1536][512]
__device__ __half g_woutT[262144];     // [512][512]

// ------------------------------ helpers -----------------------------------
__device__ __forceinline__ float tf32r(float f) {
    unsigned u;
    asm("cvt.rna.tf32.f32 %0, %1;" : "=r"(u) : "f"(f));
    return __uint_as_float(u);
}
__device__ __forceinline__ uint32_t smem_u32(const void* p) {
    uint32_t a;
    asm("{ .reg .u64 t; cvta.to.shared.u64 t, %1; cvt.u32.u64 %0, t; }"
        : "=r"(a) : "l"(p));
    return a;
}
__device__ __forceinline__ void cp16(uint32_t dst, const void* src) {
    asm volatile("cp.async.cg.shared.global [%0], [%1], 16;\n"
                 :: "r"(dst), "l"(src));
}
#define CP_COMMIT() asm volatile("cp.async.commit_group;\n" ::: "memory")
#define CP_WAIT(n)  asm volatile("cp.async.wait_group %0;\n" :: "n"(n) : "memory")

__device__ __forceinline__ void ldsm4(unsigned* r, uint32_t a) {
    asm volatile("ldmatrix.sync.aligned.m8n8.x4.shared.b16 {%0,%1,%2,%3}, [%4];"
                 : "=r"(r[0]), "=r"(r[1]), "=r"(r[2]), "=r"(r[3]) : "r"(a));
}
__device__ __forceinline__ void mma_f16(float* d, const unsigned* a, const unsigned* b) {
    asm volatile(
        "mma.sync.aligned.m16n8k16.row.col.f32.f16.f16.f32 "
        "{%0,%1,%2,%3}, {%4,%5,%6,%7}, {%8,%9}, {%0,%1,%2,%3};\n"
        : "+f"(d[0]), "+f"(d[1]), "+f"(d[2]), "+f"(d[3])
        : "r"(a[0]), "r"(a[1]), "r"(a[2]), "r"(a[3]),
          "r"(b[0]), "r"(b[1]));
}
__device__ __forceinline__ void mma_tf32(float* d, const unsigned* a, const unsigned* b) {
    asm volatile(
        "mma.sync.aligned.m16n8k8.row.col.f32.tf32.tf32.f32 "
        "{%0,%1,%2,%3}, {%4,%5,%6,%7}, {%8,%9}, {%0,%1,%2,%3};\n"
        : "+f"(d[0]), "+f"(d[1]), "+f"(d[2]), "+f"(d[3])
        : "r"(a[0]), "r"(a[1]), "r"(a[2]), "r"(a[3]),
          "r"(b[0]), "r"(b[1]));
}

__device__ __forceinline__ void storeC(float* C, size_t idx, float a, float b) {
    *(float2*)(C + idx) = make_float2(a, b);
}
__device__ __forceinline__ void storeC(__half* C, size_t idx, float a, float b) {
    *(__half2*)(C + idx) = __floats2half2_rn(a, b);
}

// ----------------------------- GEMM (fp16) ---------------------------------
// CTA 128x128, BK=32, 128 threads = 4 warps (2x2), warp tile 64x64.
// 4-stage cp.async ring, wait_group(2), ONE __syncthreads per stage.
// A [M][512] half row-major; B = WT [N][512] half row-major.
#define BM 128
#define BN 128
#define BK 32
#define RSH 40
#define OP_HALVES (128 * RSH)          // 5120 per operand per stage
#define STG_HALVES (2 * OP_HALVES)     // A|B per stage
#define STG_BYTES (STG_HALVES * 2)     // 20480
#define NSTG 4
#define GSMEM_BYTES (NSTG * STG_BYTES) // 81920

template <typename OutT>
__global__ void __launch_bounds__(128)
gemm_f16(const __half* __restrict__ A, const __half* __restrict__ B,
         OutT* __restrict__ C, int Mreal, int N)
{
    extern __shared__ __half sm[];

    const int tid  = threadIdx.x;
    const int lane = tid & 31;
    const int warp = tid >> 5;          // 0..3
    const int wm   = warp >> 1;
    const int wn   = warp & 1;
    const int grp  = lane >> 2;
    const int tg   = lane & 3;

    const int m0 = blockIdx.y * BM;
    const int n0 = blockIdx.x * BN;
    const uint32_t smb = smem_u32(sm);

    // conflict-free fill: warp covers 8 rows x 64B; lane -> row=lane&7, chunk=lane>>3
    const int frow = warp * 8 + (lane & 7);     // base row, reps +32p (p<4)
    const int fc   = (lane >> 3) << 3;          // halves: 0,8,16,24
    const __half*  ag0 = A + (size_t)(m0 + frow) * KDIM + fc;
    const __half*  bg0 = B + (size_t)(n0 + frow) * KDIM + fc;
    const uint32_t ad0 = smb + (uint32_t)((frow * RSH + fc) * 2);
    const uint32_t bd0 = ad0 + OP_HALVES * 2;

    // ldmatrix lane->address components
    const int l7 = lane & 7;
    const int lb = (lane >> 3) & 1;
    const int lt = lane >> 4;
    const uint32_t aL = smb +
        (uint32_t)(((wm * 64 + l7 + lb * 8) * RSH + lt * 8) * 2);
    const uint32_t bL = smb + (uint32_t)(OP_HALVES * 2) +
        (uint32_t)(((wn * 64 + l7 + lt * 8) * RSH + lb * 8) * 2);

    float acc[4][8][4];
    #pragma unroll
    for (int i = 0; i < 4; i++)
        #pragma unroll
        for (int j = 0; j < 8; j++)
            #pragma unroll
            for (int l = 0; l < 4; l++) acc[i][j][l] = 0.f;

    const int T = KDIM / BK;   // 16

    // prologue: stages 0..2
    #pragma unroll
    for (int s = 0; s < NSTG - 1; s++) {
        const uint32_t ad = ad0 + (uint32_t)(s * STG_BYTES);
        const uint32_t bd = bd0 + (uint32_t)(s * STG_BYTES);
        const __half* ag = ag0 + s * BK;
        const __half* bg = bg0 + s * BK;
        #pragma unroll
        for (int p = 0; p < 4; p++) {
            cp16(ad + (uint32_t)(p * 32 * RSH) * 2, ag + (size_t)p * 32 * KDIM);
            cp16(bd + (uint32_t)(p * 32 * RSH) * 2, bg + (size_t)p * 32 * KDIM);
        }
        CP_COMMIT();
    }

    for (int t = 0; t < T; ++t) {
        // ensure stage t landed
        if (t < T - 2)      { CP_WAIT(2); }
        else if (t == T - 2){ CP_WAIT(1); }
        else                { CP_WAIT(0); }
        __syncthreads();

        // prefetch stage t+3 into buffer (t+3)&3  (safe: that buffer was last
        // read at iter t-1, and every thread passed this iteration's sync)
        if (t + NSTG - 1 < T) {
            const int s = t + NSTG - 1;
            const uint32_t off = (uint32_t)((s & (NSTG - 1)) * STG_BYTES);
            const __half* ag = ag0 + s * BK;
            const __half* bg = bg0 + s * BK;
            #pragma unroll
            for (int p = 0; p < 4; p++) {
                cp16(ad0 + off + (uint32_t)(p * 32 * RSH) * 2, ag + (size_t)p * 32 * KDIM);
                cp16(bd0 + off + (uint32_t)(p * 32 * RSH) * 2, bg + (size_t)p * 32 * KDIM);
            }
            CP_COMMIT();
        }

        const uint32_t bufo = (uint32_t)((t & (NSTG - 1)) * STG_BYTES);
        const uint32_t aB = aL + bufo;
        const uint32_t bB = bL + bufo;
        #pragma unroll
        for (int ks = 0; ks < 2; ks++) {
            const uint32_t kkb = (uint32_t)(ks * 32);     // 16 halves
            unsigned af[4][4], bf[8][2];
            #pragma unroll
            for (int mt = 0; mt < 4; mt++)
                ldsm4(af[mt], aB + (uint32_t)(mt * 16 * RSH * 2) + kkb);
            #pragma unroll
            for (int np = 0; np < 4; np++) {
                unsigned r[4];
                ldsm4(r, bB + (uint32_t)(np * 16 * RSH * 2) + kkb);
                bf[2 * np][0] = r[0]; bf[2 * np][1] = r[1];
                bf[2 * np + 1][0] = r[2]; bf[2 * np + 1][1] = r[3];
            }
            #pragma unroll
            for (int mt = 0; mt < 4; mt++)
                #pragma unroll
                for (int nt = 0; nt < 8; nt++)
                    mma_f16(acc[mt][nt], af[mt], bf[nt]);
        }
    }

    #pragma unroll
    for (int mt = 0; mt < 4; mt++) {
        #pragma unroll
        for (int nt = 0; nt < 8; nt++) {
            int r0 = m0 + wm * 64 + mt * 16 + grp;
            int c  = n0 + wn * 64 + nt * 8 + tg * 2;
            if (r0 < Mreal)
                storeC(C, (size_t)r0 * N + c, acc[mt][nt][0], acc[mt][nt][1]);
            if (r0 + 8 < Mreal)
                storeC(C, (size_t)(r0 + 8) * N + c, acc[mt][nt][2], acc[mt][nt][3]);
        }
    }
}

// ------------------------------ prep kernels -------------------------------
__global__ void half_pad(const float* __restrict__ x, __half* __restrict__ xh,
                         long nreal, long ntot)
{
    long i = (long)blockIdx.x * blockDim.x + threadIdx.x;
    if (i < ntot) xh[i] = __float2half((i < nreal) ? x[i] : 0.f);
}

__global__ void transpose_half(const float* __restrict__ W, __half* __restrict__ WT,
                               int R, int Ccols)
{
    __shared__ float t[32][33];
    const int tx = threadIdx.x, ty = threadIdx.y;
    const int x = blockIdx.x * 32 + tx;
    #pragma unroll
    for (int j = 0; j < 4; j++) {
        int y = blockIdx.y * 32 + ty + j * 8;
        t[ty + j * 8][tx] = W[(size_t)y * Ccols + x];
    }
    __syncthreads();
    const int ox = blockIdx.y * 32 + tx;
    #pragma unroll
    for (int j = 0; j < 4; j++) {
        int oy = blockIdx.x * 32 + ty + j * 8;
        WT[(size_t)oy * R + ox] = __float2half(t[tx][ty + j * 8]);
    }
}

__global__ void zero_fill_h(__half* __restrict__ p, int n)
{
    int i = blockIdx.x * blockDim.x + threadIdx.x;
    if (i < n / 2) ((uint32_t*)p)[i] = 0u;
}

// ----------------------------- attention (tf32 HMMA, half I/O) -------------
#define QST 36
#define KST 36
#define VST 40
#define PST 60

__device__ __forceinline__ int div7(int v) { return (v * 37) >> 8; }  // exact 0..55

__global__ void __launch_bounds__(128)
attn_mma(const __half* __restrict__ qkv,
         const float* __restrict__ bias_table,
         __half* __restrict__ att)
{
    __shared__ float Qs[64 * QST];
    __shared__ float Ks[56 * KST];
    __shared__ float Vs[56 * VST];
    __shared__ float Ps[64 * PST];
    __shared__ float bs[176];
    __shared__ float inv[64];

    const int h  = blockIdx.x & 15;
    const int bw = blockIdx.x >> 4;
    const int tid  = threadIdx.x;
    const int lane = tid & 31;
    const int wm   = tid >> 5;
    const int grp  = lane >> 2;
    const int tg   = lane & 3;

    const __half* base = qkv + (size_t)bw * WIN * 1536 + h * 32;
    const float SCALE = 0.17677669529663687f;

    for (int l = tid; l < WIN * 4; l += 128) {
        int i = l >> 2, c = l & 3;
        const __half2* qrow = (const __half2*)(base + (size_t)i * 1536) + c * 4;
        const __half2* krow = (const __half2*)(base + (size_t)i * 1536 + 512) + c * 4;
        const __half2* vrow = (const __half2*)(base + (size_t)i * 1536 + 1024) + c * 4;
        #pragma unroll
        for (int q = 0; q < 4; q++) {
            float2 qf = __half22float2(qrow[q]);
            Qs[i * QST + c * 8 + 2 * q]     = tf32r(qf.x * SCALE);
            Qs[i * QST + c * 8 + 2 * q + 1] = tf32r(qf.y * SCALE);
            float2 kf = __half22float2(krow[q]);
            Ks[i * KST + c * 8 + 2 * q]     = kf.x;
            Ks[i * KST + c * 8 + 2 * q + 1] = kf.y;
            float2 vf = __half22float2(vrow[q]);
            Vs[i * VST + c * 8 + 2 * q]     = vf.x;
            Vs[i * VST + c * 8 + 2 * q + 1] = vf.y;
        }
    }
    const float4 z4 = make_float4(0.f, 0.f, 0.f, 0.f);
    for (int l = tid; l < 15 * 8; l += 128) {
        int i = WIN + (l >> 3), c = l & 7;
        *(float4*)(Qs + i * QST + c * 4) = z4;
        if (i < 56) {
            *(float4*)(Ks + i * KST + c * 4) = z4;
            *(float4*)(Vs + i * VST + c * 4) = z4;
        }
    }
    for (int l = tid; l < 169; l += 128) bs[l] = bias_table[l * HEADS + h];
    __syncthreads();

    const int i0 = wm * 16 + grp;
    const int i1 = i0 + 8;
    const int ri0 = div7(i0), ci0 = i0 - ri0 * 7;
    const int ri1 = div7(i1), ci1 = i1 - ri1 * 7;

    float c[7][4];
    #pragma unroll
    for (int nt = 0; nt < 7; nt++)
        #pragma unroll
        for (int l = 0; l < 4; l++) c[nt][l] = 0.f;

    #pragma unroll
    for (int ks = 0; ks < 4; ks++) {
        const int kk = ks * 8;
        unsigned a[4];
        a[0] = __float_as_uint(Qs[i0 * QST + kk + tg]);
        a[1] = __float_as_uint(Qs[i1 * QST + kk + tg]);
        a[2] = __float_as_uint(Qs[i0 * QST + kk + tg + 4]);
        a[3] = __float_as_uint(Qs[i1 * QST + kk + tg + 4]);
        #pragma unroll
        for (int nt = 0; nt < 7; nt++) {
            const int j = nt * 8 + grp;
            unsigned b[2];
            b[0] = __float_as_uint(Ks[j * KST + kk + tg]);
            b[1] = __float_as_uint(Ks[j * KST + kk + tg + 4]);
            mma_tf32(c[nt], a, b);
        }
    }

    float s01 = 0.f, s23 = 0.f;
    #pragma unroll
    for (int nt = 0; nt < 7; nt++) {
        const int j0 = nt * 8 + 2 * tg;
        const int j1 = j0 + 1;
        const int rj0 = div7(j0), cj0 = j0 - rj0 * 7;
        const int rj1 = div7(j1), cj1 = j1 - rj1 * 7;
        float e00 = 0.f, e01 = 0.f, e10 = 0.f, e11 = 0.f;
        if (j0 < WIN) {
            e00 = __expf(c[nt][0] + bs[(ri0 - rj0 + 6) * 13 + (ci0 - cj0 + 6)]);
            e10 = __expf(c[nt][2] + bs[(ri1 - rj0 + 6) * 13 + (ci1 - cj0 + 6)]);
        }
        if (j1 < WIN) {
            e01 = __expf(c[nt][1] + bs[(ri0 - rj1 + 6) * 13 + (ci0 - cj1 + 6)]);
            e11 = __expf(c[nt][3] + bs[(ri1 - rj1 + 6) * 13 + (ci1 - cj1 + 6)]);
        }
        s01 += e00 + e01;
        s23 += e10 + e11;
        *(float2*)(Ps + i0 * PST + j0) = make_float2(tf32r(e00), tf32r(e01));
        *(float2*)(Ps + i1 * PST + j0) = make_float2(tf32r(e10), tf32r(e11));
    }
    s01 += __shfl_xor_sync(0xFFFFFFFFu, s01, 1);
    s01 += __shfl_xor_sync(0xFFFFFFFFu, s01, 2);
    s23 += __shfl_xor_sync(0xFFFFFFFFu, s23, 1);
    s23 += __shfl_xor_sync(0xFFFFFFFFu, s23, 2);
    if (tg == 0) {
        inv[i0] = 1.f / s01;
        inv[i1] = 1.f / s23;
    }
    __syncwarp();

    float o[4][4];
    #pragma unroll
    for (int nt = 0; nt < 4; nt++)
        #pragma unroll
        for (int l = 0; l < 4; l++) o[nt][l] = 0.f;

    #pragma unroll
    for (int ks = 0; ks < 7; ks++) {
        const int kk = ks * 8;
        unsigned a[4];
        a[0] = __float_as_uint(Ps[i0 * PST + kk + tg]);
        a[1] = __float_as_uint(Ps[i1 * PST + kk + tg]);
        a[2] = __float_as_uint(Ps[i0 * PST + kk + tg + 4]);
        a[3] = __float_as_uint(Ps[i1 * PST + kk + tg + 4]);
        #pragma unroll
        for (int nt = 0; nt < 4; nt++) {
            unsigned b[2];
            b[0] = __float_as_uint(Vs[(kk + tg)     * VST + nt * 8 + grp]);
            b[1] = __float_as_uint(Vs[(kk + tg + 4) * VST + nt * 8 + grp]);
            mma_tf32(o[nt], a, b);
        }
    }

    const float v0 = inv[i0];
    const float v1 = inv[i1];
    __half* obase = att + (size_t)bw * WIN * 512 + h * 32;
    #pragma unroll
    for (int nt = 0; nt < 4; nt++) {
        const int d0 = nt * 8 + 2 * tg;
        if (i0 < WIN)
            *(__half2*)(obase + (size_t)i0 * 512 + d0) =
                __floats2half2_rn(o[nt][0] * v0, o[nt][1] * v0);
        if (i1 < WIN)
            *(__half2*)(obase + (size_t)i1 * 512 + d0) =
                __floats2half2_rn(o[nt][2] * v1, o[nt][3] * v1);
    }
}

// --------------------------------- launcher --------------------------------
extern "C" void kernel_launch(void* const* d_in, const int* in_sizes, int n_in,
                              void* d_out, int out_size)
{
    const float* x          = (const float*)d_in[0];
    const float* w_qkv      = (const float*)d_in[1];
    const float* bias_table = (const float*)d_in[2];
    const float* w_out      = (const float*)d_in[3];
    float* out = (float*)d_out;

    __half *qkvh, *atth, *xh, *wqkvT, *woutT;
    cudaGetSymbolAddress((void**)&qkvh,  g_qkvh);
    cudaGetSymbolAddress((void**)&atth,  g_atth);
    cudaGetSymbolAddress((void**)&xh,    g_xh);
    cudaGetSymbolAddress((void**)&wqkvT, g_wqkvT);
    cudaGetSymbolAddress((void**)&woutT, g_woutT);

    cudaFuncSetAttribute(gemm_f16<__half>,
                         cudaFuncAttributeMaxDynamicSharedMemorySize, GSMEM_BYTES);
    cudaFuncSetAttribute(gemm_f16<float>,
                         cudaFuncAttributeMaxDynamicSharedMemorySize, GSMEM_BYTES);

    const long nreal = (long)M_REAL * 512;
    const long ntot  = (long)M_PAD  * 512;

    // order chosen so the ncu fixed capture slot (previously zero_fill_h)
    // lands on gemm K1; zero_fill only writes att pad rows -> legal before K3.
    half_pad<<<(int)((ntot + 255) / 256), 256>>>(x, xh, nreal, ntot);
    transpose_half<<<dim3(1536 / 32, 512 / 32), dim3(32, 8)>>>(w_qkv, wqkvT, 512, 1536);
    transpose_half<<<dim3(512 / 32, 512 / 32), dim3(32, 8)>>>(w_out, woutT, 512, 512);

    // K1: qkvh = xh @ wqkvT^T
    gemm_f16<__half><<<dim3(1536 / BN, M_PAD / BM), 128, GSMEM_BYTES>>>(
        xh, wqkvT, qkvh, M_REAL, 1536);

    zero_fill_h<<<(64 * 512 / 2 + 255) / 256, 256>>>(atth + nreal, 64 * 512);

    // K2: attention
    attn_mma<<<NWIN * HEADS, 128>>>(qkvh, bias_table, atth);

    // K3: out = atth @ woutT^T
    gemm_f16<float><<<dim3(512 / BN, M_PAD / BM), 128, GSMEM_BYTES>>>(
        atth, woutT, out, M_REAL, 512);
}

// round 12
// speedup vs baseline: 1.1153x; 1.0734x over previous
#include <cuda_runtime.h>
#include <cuda_fp16.h>
#include <cstdint>

// ---------------------------------------------------------------------------
// MultiAxisAttention (Swin window attention) — fp16 HMMA GEMMs, m16n8k16,
// fp32 accumulate. R12 = R11 with 3-stage ring (60KB smem) + launch_bounds
// minBlocks=3 -> 3 CTAs/SM (occupancy fix; ncu R11: occ 12.3%, issue 13.7%).
// Attention = R8-proven tf32 HMMA with half I/O.
// ---------------------------------------------------------------------------

#define M_REAL 153664            // 16*196*49
#define M_PAD  153728            // 1201*128
#define NWIN   3136
#define HEADS  16
#define WIN    49
#define KDIM   512

__device__ __half g_qkvh[236027904];   // M_REAL*1536
__device__ __half g_atth[78708736];    // M_PAD*512 (pad rows zeroed)
__device__ __half g_xh  [78708736];    // M_PAD*512 (pad rows zeroed)
__device__ __half g_wqkvT[786432];     // [1536][512]
__device__ __half g_woutT[262144];     // [512][512]

// ------------------------------ helpers -----------------------------------
__device__ __forceinline__ float tf32r(float f) {
    unsigned u;
    asm("cvt.rna.tf32.f32 %0, %1;" : "=r"(u) : "f"(f));
    return __uint_as_float(u);
}
__device__ __forceinline__ uint32_t smem_u32(const void* p) {
    uint32_t a;
    asm("{ .reg .u64 t; cvta.to.shared.u64 t, %1; cvt.u32.u64 %0, t; }"
        : "=r"(a) : "l"(p));
    return a;
}
__device__ __forceinline__ void cp16(uint32_t dst, const void* src) {
    asm volatile("cp.async.cg.shared.global [%0], [%1], 16;\n"
                 :: "r"(dst), "l"(src));
}
#define CP_COMMIT() asm volatile("cp.async.commit_group;\n" ::: "memory")
#define CP_WAIT(n)  asm volatile("cp.async.wait_group %0;\n" :: "n"(n) : "memory")

__device__ __forceinline__ void ldsm4(unsigned* r, uint32_t a) {
    asm volatile("ldmatrix.sync.aligned.m8n8.x4.shared.b16 {%0,%1,%2,%3}, [%4];"
                 : "=r"(r[0]), "=r"(r[1]), "=r"(r[2]), "=r"(r[3]) : "r"(a));
}
__device__ __forceinline__ void mma_f16(float* d, const unsigned* a, const unsigned* b) {
    asm volatile(
        "mma.sync.aligned.m16n8k16.row.col.f32.f16.f16.f32 "
        "{%0,%1,%2,%3}, {%4,%5,%6,%7}, {%8,%9}, {%0,%1,%2,%3};\n"
        : "+f"(d[0]), "+f"(d[1]), "+f"(d[2]), "+f"(d[3])
        : "r"(a[0]), "r"(a[1]), "r"(a[2]), "r"(a[3]),
          "r"(b[0]), "r"(b[1]));
}
__device__ __forceinline__ void mma_tf32(float* d, const unsigned* a, const unsigned* b) {
    asm volatile(
        "mma.sync.aligned.m16n8k8.row.col.f32.tf32.tf32.f32 "
        "{%0,%1,%2,%3}, {%4,%5,%6,%7}, {%8,%9}, {%0,%1,%2,%3};\n"
        : "+f"(d[0]), "+f"(d[1]), "+f"(d[2]), "+f"(d[3])
        : "r"(a[0]), "r"(a[1]), "r"(a[2]), "r"(a[3]),
          "r"(b[0]), "r"(b[1]));
}

__device__ __forceinline__ void storeC(float* C, size_t idx, float a, float b) {
    *(float2*)(C + idx) = make_float2(a, b);
}
__device__ __forceinline__ void storeC(__half* C, size_t idx, float a, float b) {
    *(__half2*)(C + idx) = __floats2half2_rn(a, b);
}

// ----------------------------- GEMM (fp16) ---------------------------------
// CTA 128x128, BK=32, 128 threads = 4 warps (2x2), warp tile 64x64.
// 3-stage cp.async ring, wait_group(1), ONE __syncthreads per stage.
// A [M][512] half row-major; B = WT [N][512] half row-major.
#define BM 128
#define BN 128
#define BK 32
#define RSH 40
#define OP_HALVES (128 * RSH)          // 5120 per operand per stage
#define STG_HALVES (2 * OP_HALVES)     // A|B per stage
#define STG_BYTES (STG_HALVES * 2)     // 20480
#define NSTG 3
#define GSMEM_BYTES (NSTG * STG_BYTES) // 61440

template <typename OutT>
__global__ void __launch_bounds__(128, 3)
gemm_f16(const __half* __restrict__ A, const __half* __restrict__ B,
         OutT* __restrict__ C, int Mreal, int N)
{
    extern __shared__ __half sm[];

    const int tid  = threadIdx.x;
    const int lane = tid & 31;
    const int warp = tid >> 5;          // 0..3
    const int wm   = warp >> 1;
    const int wn   = warp & 1;
    const int grp  = lane >> 2;
    const int tg   = lane & 3;

    const int m0 = blockIdx.y * BM;
    const int n0 = blockIdx.x * BN;
    const uint32_t smb = smem_u32(sm);

    // conflict-free fill: warp covers 8 rows x 64B; lane -> row=lane&7, chunk=lane>>3
    const int frow = warp * 8 + (lane & 7);     // base row, reps +32p (p<4)
    const int fc   = (lane >> 3) << 3;          // halves: 0,8,16,24
    const __half*  ag0 = A + (size_t)(m0 + frow) * KDIM + fc;
    const __half*  bg0 = B + (size_t)(n0 + frow) * KDIM + fc;
    const uint32_t ad0 = smb + (uint32_t)((frow * RSH + fc) * 2);
    const uint32_t bd0 = ad0 + OP_HALVES * 2;

    // ldmatrix lane->address components
    const int l7 = lane & 7;
    const int lb = (lane >> 3) & 1;
    const int lt = lane >> 4;
    const uint32_t aL = smb +
        (uint32_t)(((wm * 64 + l7 + lb * 8) * RSH + lt * 8) * 2);
    const uint32_t bL = smb + (uint32_t)(OP_HALVES * 2) +
        (uint32_t)(((wn * 64 + l7 + lt * 8) * RSH + lb * 8) * 2);

    float acc[4][8][4];
    #pragma unroll
    for (int i = 0; i < 4; i++)
        #pragma unroll
        for (int j = 0; j < 8; j++)
            #pragma unroll
            for (int l = 0; l < 4; l++) acc[i][j][l] = 0.f;

    const int T = KDIM / BK;   // 16

    // prologue: stages 0,1
    #pragma unroll
    for (int s = 0; s < NSTG - 1; s++) {
        const uint32_t ad = ad0 + (uint32_t)(s * STG_BYTES);
        const uint32_t bd = bd0 + (uint32_t)(s * STG_BYTES);
        const __half* ag = ag0 + s * BK;
        const __half* bg = bg0 + s * BK;
        #pragma unroll
        for (int p = 0; p < 4; p++) {
            cp16(ad + (uint32_t)(p * 32 * RSH) * 2, ag + (size_t)p * 32 * KDIM);
            cp16(bd + (uint32_t)(p * 32 * RSH) * 2, bg + (size_t)p * 32 * KDIM);
        }
        CP_COMMIT();
    }

    int bc = 0;   // t % 3
    int pb = 2;   // (t+2) % 3
    for (int t = 0; t < T; ++t) {
        if (t < T - 1) { CP_WAIT(1); } else { CP_WAIT(0); }
        __syncthreads();

        // prefetch stage t+2 into buffer (t+2)%3 (last read at iter t-1;
        // every thread passed this iteration's sync -> safe)
        if (t + NSTG - 1 < T) {
            const int s = t + NSTG - 1;
            const uint32_t off = (uint32_t)(pb * STG_BYTES);
            const __half* ag = ag0 + s * BK;
            const __half* bg = bg0 + s * BK;
            #pragma unroll
            for (int p = 0; p < 4; p++) {
                cp16(ad0 + off + (uint32_t)(p * 32 * RSH) * 2, ag + (size_t)p * 32 * KDIM);
                cp16(bd0 + off + (uint32_t)(p * 32 * RSH) * 2, bg + (size_t)p * 32 * KDIM);
            }
            CP_COMMIT();
        }

        const uint32_t bufo = (uint32_t)(bc * STG_BYTES);
        const uint32_t aB = aL + bufo;
        const uint32_t bB = bL + bufo;
        #pragma unroll
        for (int ks = 0; ks < 2; ks++) {
            const uint32_t kkb = (uint32_t)(ks * 32);     // 16 halves
            unsigned af[4][4], bf[8][2];
            #pragma unroll
            for (int mt = 0; mt < 4; mt++)
                ldsm4(af[mt], aB + (uint32_t)(mt * 16 * RSH * 2) + kkb);
            #pragma unroll
            for (int np = 0; np < 4; np++) {
                unsigned r[4];
                ldsm4(r, bB + (uint32_t)(np * 16 * RSH * 2) + kkb);
                bf[2 * np][0] = r[0]; bf[2 * np][1] = r[1];
                bf[2 * np + 1][0] = r[2]; bf[2 * np + 1][1] = r[3];
            }
            #pragma unroll
            for (int mt = 0; mt < 4; mt++)
                #pragma unroll
                for (int nt = 0; nt < 8; nt++)
                    mma_f16(acc[mt][nt], af[mt], bf[nt]);
        }

        bc = (bc == 2) ? 0 : bc + 1;
        pb = (pb == 2) ? 0 : pb + 1;
    }

    #pragma unroll
    for (int mt = 0; mt < 4; mt++) {
        #pragma unroll
        for (int nt = 0; nt < 8; nt++) {
            int r0 = m0 + wm * 64 + mt * 16 + grp;
            int c  = n0 + wn * 64 + nt * 8 + tg * 2;
            if (r0 < Mreal)
                storeC(C, (size_t)r0 * N + c, acc[mt][nt][0], acc[mt][nt][1]);
            if (r0 + 8 < Mreal)
                storeC(C, (size_t)(r0 + 8) * N + c, acc[mt][nt][2], acc[mt][nt][3]);
        }
    }
}

// ------------------------------ prep kernels -------------------------------
__global__ void half_pad(const float* __restrict__ x, __half* __restrict__ xh,
                         long nreal, long ntot)
{
    long i = (long)blockIdx.x * blockDim.x + threadIdx.x;
    if (i < ntot) xh[i] = __float2half((i < nreal) ? x[i] : 0.f);
}

__global__ void transpose_half(const float* __restrict__ W, __half* __restrict__ WT,
                               int R, int Ccols)
{
    __shared__ float t[32][33];
    const int tx = threadIdx.x, ty = threadIdx.y;
    const int x = blockIdx.x * 32 + tx;
    #pragma unroll
    for (int j = 0; j < 4; j++) {
        int y = blockIdx.y * 32 + ty + j * 8;
        t[ty + j * 8][tx] = W[(size_t)y * Ccols + x];
    }
    __syncthreads();
    const int ox = blockIdx.y * 32 + tx;
    #pragma unroll
    for (int j = 0; j < 4; j++) {
        int oy = blockIdx.x * 32 + ty + j * 8;
        WT[(size_t)oy * R + ox] = __float2half(t[tx][ty + j * 8]);
    }
}

__global__ void zero_fill_h(__half* __restrict__ p, int n)
{
    int i = blockIdx.x * blockDim.x + threadIdx.x;
    if (i < n / 2) ((uint32_t*)p)[i] = 0u;
}

// ----------------------------- attention (tf32 HMMA, half I/O) -------------
#define QST 36
#define KST 36
#define VST 40
#define PST 60

__device__ __forceinline__ int div7(int v) { return (v * 37) >> 8; }  // exact 0..55

__global__ void __launch_bounds__(128)
attn_mma(const __half* __restrict__ qkv,
         const float* __restrict__ bias_table,
         __half* __restrict__ att)
{
    __shared__ float Qs[64 * QST];
    __shared__ float Ks[56 * KST];
    __shared__ float Vs[56 * VST];
    __shared__ float Ps[64 * PST];
    __shared__ float bs[176];
    __shared__ float inv[64];

    const int h  = blockIdx.x & 15;
    const int bw = blockIdx.x >> 4;
    const int tid  = threadIdx.x;
    const int lane = tid & 31;
    const int wm   = tid >> 5;
    const int grp  = lane >> 2;
    const int tg   = lane & 3;

    const __half* base = qkv + (size_t)bw * WIN * 1536 + h * 32;
    const float SCALE = 0.17677669529663687f;

    for (int l = tid; l < WIN * 4; l += 128) {
        int i = l >> 2, c = l & 3;
        const __half2* qrow = (const __half2*)(base + (size_t)i * 1536) + c * 4;
        const __half2* krow = (const __half2*)(base + (size_t)i * 1536 + 512) + c * 4;
        const __half2* vrow = (const __half2*)(base + (size_t)i * 1536 + 1024) + c * 4;
        #pragma unroll
        for (int q = 0; q < 4; q++) {
            float2 qf = __half22float2(qrow[q]);
            Qs[i * QST + c * 8 + 2 * q]     = tf32r(qf.x * SCALE);
            Qs[i * QST + c * 8 + 2 * q + 1] = tf32r(qf.y * SCALE);
            float2 kf = __half22float2(krow[q]);
            Ks[i * KST + c * 8 + 2 * q]     = kf.x;
            Ks[i * KST + c * 8 + 2 * q + 1] = kf.y;
            float2 vf = __half22float2(vrow[q]);
            Vs[i * VST + c * 8 + 2 * q]     = vf.x;
            Vs[i * VST + c * 8 + 2 * q + 1] = vf.y;
        }
    }
    const float4 z4 = make_float4(0.f, 0.f, 0.f, 0.f);
    for (int l = tid; l < 15 * 8; l += 128) {
        int i = WIN + (l >> 3), c = l & 7;
        *(float4*)(Qs + i * QST + c * 4) = z4;
        if (i < 56) {
            *(float4*)(Ks + i * KST + c * 4) = z4;
            *(float4*)(Vs + i * VST + c * 4) = z4;
        }
    }
    for (int l = tid; l < 169; l += 128) bs[l] = bias_table[l * HEADS + h];
    __syncthreads();

    const int i0 = wm * 16 + grp;
    const int i1 = i0 + 8;
    const int ri0 = div7(i0), ci0 = i0 - ri0 * 7;
    const int ri1 = div7(i1), ci1 = i1 - ri1 * 7;

    float c[7][4];
    #pragma unroll
    for (int nt = 0; nt < 7; nt++)
        #pragma unroll
        for (int l = 0; l < 4; l++) c[nt][l] = 0.f;

    #pragma unroll
    for (int ks = 0; ks < 4; ks++) {
        const int kk = ks * 8;
        unsigned a[4];
        a[0] = __float_as_uint(Qs[i0 * QST + kk + tg]);
        a[1] = __float_as_uint(Qs[i1 * QST + kk + tg]);
        a[2] = __float_as_uint(Qs[i0 * QST + kk + tg + 4]);
        a[3] = __float_as_uint(Qs[i1 * QST + kk + tg + 4]);
        #pragma unroll
        for (int nt = 0; nt < 7; nt++) {
            const int j = nt * 8 + grp;
            unsigned b[2];
            b[0] = __float_as_uint(Ks[j * KST + kk + tg]);
            b[1] = __float_as_uint(Ks[j * KST + kk + tg + 4]);
            mma_tf32(c[nt], a, b);
        }
    }

    float s01 = 0.f, s23 = 0.f;
    #pragma unroll
    for (int nt = 0; nt < 7; nt++) {
        const int j0 = nt * 8 + 2 * tg;
        const int j1 = j0 + 1;
        const int rj0 = div7(j0), cj0 = j0 - rj0 * 7;
        const int rj1 = div7(j1), cj1 = j1 - rj1 * 7;
        float e00 = 0.f, e01 = 0.f, e10 = 0.f, e11 = 0.f;
        if (j0 < WIN) {
            e00 = __expf(c[nt][0] + bs[(ri0 - rj0 + 6) * 13 + (ci0 - cj0 + 6)]);
            e10 = __expf(c[nt][2] + bs[(ri1 - rj0 + 6) * 13 + (ci1 - cj0 + 6)]);
        }
        if (j1 < WIN) {
            e01 = __expf(c[nt][1] + bs[(ri0 - rj1 + 6) * 13 + (ci0 - cj1 + 6)]);
            e11 = __expf(c[nt][3] + bs[(ri1 - rj1 + 6) * 13 + (ci1 - cj1 + 6)]);
        }
        s01 += e00 + e01;
        s23 += e10 + e11;
        *(float2*)(Ps + i0 * PST + j0) = make_float2(tf32r(e00), tf32r(e01));
        *(float2*)(Ps + i1 * PST + j0) = make_float2(tf32r(e10), tf32r(e11));
    }
    s01 += __shfl_xor_sync(0xFFFFFFFFu, s01, 1);
    s01 += __shfl_xor_sync(0xFFFFFFFFu, s01, 2);
    s23 += __shfl_xor_sync(0xFFFFFFFFu, s23, 1);
    s23 += __shfl_xor_sync(0xFFFFFFFFu, s23, 2);
    if (tg == 0) {
        inv[i0] = 1.f / s01;
        inv[i1] = 1.f / s23;
    }
    __syncwarp();

    float o[4][4];
    #pragma unroll
    for (int nt = 0; nt < 4; nt++)
        #pragma unroll
        for (int l = 0; l < 4; l++) o[nt][l] = 0.f;

    #pragma unroll
    for (int ks = 0; ks < 7; ks++) {
        const int kk = ks * 8;
        unsigned a[4];
        a[0] = __float_as_uint(Ps[i0 * PST + kk + tg]);
        a[1] = __float_as_uint(Ps[i1 * PST + kk + tg]);
        a[2] = __float_as_uint(Ps[i0 * PST + kk + tg + 4]);
        a[3] = __float_as_uint(Ps[i1 * PST + kk + tg + 4]);
        #pragma unroll
        for (int nt = 0; nt < 4; nt++) {
            unsigned b[2];
            b[0] = __float_as_uint(Vs[(kk + tg)     * VST + nt * 8 + grp]);
            b[1] = __float_as_uint(Vs[(kk + tg + 4) * VST + nt * 8 + grp]);
            mma_tf32(o[nt], a, b);
        }
    }

    const float v0 = inv[i0];
    const float v1 = inv[i1];
    __half* obase = att + (size_t)bw * WIN * 512 + h * 32;
    #pragma unroll
    for (int nt = 0; nt < 4; nt++) {
        const int d0 = nt * 8 + 2 * tg;
        if (i0 < WIN)
            *(__half2*)(obase + (size_t)i0 * 512 + d0) =
                __floats2half2_rn(o[nt][0] * v0, o[nt][1] * v0);
        if (i1 < WIN)
            *(__half2*)(obase + (size_t)i1 * 512 + d0) =
                __floats2half2_rn(o[nt][2] * v1, o[nt][3] * v1);
    }
}

// --------------------------------- launcher --------------------------------
extern "C" void kernel_launch(void* const* d_in, const int* in_sizes, int n_in,
                              void* d_out, int out_size)
{
    const float* x          = (const float*)d_in[0];
    const float* w_qkv      = (const float*)d_in[1];
    const float* bias_table = (const float*)d_in[2];
    const float* w_out      = (const float*)d_in[3];
    float* out = (float*)d_out;

    __half *qkvh, *atth, *xh, *wqkvT, *woutT;
    cudaGetSymbolAddress((void**)&qkvh,  g_qkvh);
    cudaGetSymbolAddress((void**)&atth,  g_atth);
    cudaGetSymbolAddress((void**)&xh,    g_xh);
    cudaGetSymbolAddress((void**)&wqkvT, g_wqkvT);
    cudaGetSymbolAddress((void**)&woutT, g_woutT);

    cudaFuncSetAttribute(gemm_f16<__half>,
                         cudaFuncAttributeMaxDynamicSharedMemorySize, GSMEM_BYTES);
    cudaFuncSetAttribute(gemm_f16<float>,
                         cudaFuncAttributeMaxDynamicSharedMemorySize, GSMEM_BYTES);

    const long nreal = (long)M_REAL * 512;
    const long ntot  = (long)M_PAD  * 512;

    // order keeps the ncu fixed capture slot on gemm K1
    half_pad<<<(int)((ntot + 255) / 256), 256>>>(x, xh, nreal, ntot);
    transpose_half<<<dim3(1536 / 32, 512 / 32), dim3(32, 8)>>>(w_qkv, wqkvT, 512, 1536);
    transpose_half<<<dim3(512 / 32, 512 / 32), dim3(32, 8)>>>(w_out, woutT, 512, 512);

    // K1: qkvh = xh @ wqkvT^T
    gemm_f16<__half><<<dim3(1536 / BN, M_PAD / BM), 128, GSMEM_BYTES>>>(
        xh, wqkvT, qkvh, M_REAL, 1536);

    zero_fill_h<<<(64 * 512 / 2 + 255) / 256, 256>>>(atth + nreal, 64 * 512);

    // K2: attention
    attn_mma<<<NWIN * HEADS, 128>>>(qkvh, bias_table, atth);

    // K3: out = atth @ woutT^T
    gemm_f16<float><<<dim3(512 / BN, M_PAD / BM), 128, GSMEM_BYTES>>>(
        atth, woutT, out, M_REAL, 512);
}